// round 1
// baseline (speedup 1.0000x reference)
#include <cuda_runtime.h>
#include <math.h>

#define HID    512
#define BATCH  4096
#define TSTEPS 20
#define BM 64
#define BN 64
#define BK 16

// Scratch (allocation-free rule: __device__ globals)
__device__ float g_z [BATCH * HID];
__device__ float g_dh[BATCH * HID];
__device__ float g_s [BATCH * HID];

__device__ __forceinline__ float sigmoidf(float x) { return 1.0f / (1.0f + expf(-x)); }

__global__ void copy_z_kernel(const float* __restrict__ y) {
    int i = blockIdx.x * blockDim.x + threadIdx.x;
    if (i < BATCH * HID) g_z[i] = y[i];
}

// dh = sigmoid(z@Wo^T) * tanh( sigmoid(z@Wi^T) * tanh(z@Wg^T) )
// One z-tile load in smem serves all three weight GEMMs.
__global__ __launch_bounds__(256) void fused_igo_kernel(
    const float* __restrict__ Wi, const float* __restrict__ Wg, const float* __restrict__ Wo)
{
    __shared__ float As [BK][BM];
    __shared__ float Bis[BK][BN];
    __shared__ float Bgs[BK][BN];
    __shared__ float Bos[BK][BN];

    const int bm = blockIdx.x * BM;
    const int bn = blockIdx.y * BN;
    const int tid = threadIdx.x;
    const int tx = tid & 15, ty = tid >> 4;
    const int lrow = tid >> 2;        // 0..63
    const int lk   = (tid & 3) << 2;  // 0,4,8,12

    float acc_i[4][4] = {}, acc_g[4][4] = {}, acc_o[4][4] = {};

    for (int k0 = 0; k0 < HID; k0 += BK) {
        float4 a = *(const float4*)(g_z + (bm + lrow) * HID + k0 + lk);
        As[lk+0][lrow]=a.x; As[lk+1][lrow]=a.y; As[lk+2][lrow]=a.z; As[lk+3][lrow]=a.w;
        float4 v;
        v = *(const float4*)(Wi + (bn + lrow) * HID + k0 + lk);
        Bis[lk+0][lrow]=v.x; Bis[lk+1][lrow]=v.y; Bis[lk+2][lrow]=v.z; Bis[lk+3][lrow]=v.w;
        v = *(const float4*)(Wg + (bn + lrow) * HID + k0 + lk);
        Bgs[lk+0][lrow]=v.x; Bgs[lk+1][lrow]=v.y; Bgs[lk+2][lrow]=v.z; Bgs[lk+3][lrow]=v.w;
        v = *(const float4*)(Wo + (bn + lrow) * HID + k0 + lk);
        Bos[lk+0][lrow]=v.x; Bos[lk+1][lrow]=v.y; Bos[lk+2][lrow]=v.z; Bos[lk+3][lrow]=v.w;
        __syncthreads();
        #pragma unroll
        for (int kk = 0; kk < BK; ++kk) {
            float4 av = *(const float4*)&As [kk][ty<<2];
            float4 bi = *(const float4*)&Bis[kk][tx<<2];
            float4 bg = *(const float4*)&Bgs[kk][tx<<2];
            float4 bo = *(const float4*)&Bos[kk][tx<<2];
            float aa[4]={av.x,av.y,av.z,av.w};
            float xi[4]={bi.x,bi.y,bi.z,bi.w};
            float xg[4]={bg.x,bg.y,bg.z,bg.w};
            float xo[4]={bo.x,bo.y,bo.z,bo.w};
            #pragma unroll
            for (int i = 0; i < 4; ++i) {
                #pragma unroll
                for (int j = 0; j < 4; ++j) {
                    acc_i[i][j] = fmaf(aa[i], xi[j], acc_i[i][j]);
                    acc_g[i][j] = fmaf(aa[i], xg[j], acc_g[i][j]);
                    acc_o[i][j] = fmaf(aa[i], xo[j], acc_o[i][j]);
                }
            }
        }
        __syncthreads();
    }
    #pragma unroll
    for (int i = 0; i < 4; ++i) {
        int r = bm + (ty<<2) + i;
        #pragma unroll
        for (int j = 0; j < 4; ++j) {
            int c = bn + (tx<<2) + j;
            float iv = sigmoidf(acc_i[i][j]);
            float gv = tanhf(acc_g[i][j]);
            float ov = sigmoidf(acc_o[i][j]);
            g_dh[r*HID + c] = ov * tanhf(iv * gv);
        }
    }
}

// s = dh @ Wout^T + bout
__global__ __launch_bounds__(256) void gemm_bias_kernel(
    const float* __restrict__ Wout, const float* __restrict__ bout)
{
    __shared__ float As[BK][BM];
    __shared__ float Bs[BK][BN];

    const int bm = blockIdx.x * BM;
    const int bn = blockIdx.y * BN;
    const int tid = threadIdx.x;
    const int tx = tid & 15, ty = tid >> 4;
    const int lrow = tid >> 2;
    const int lk   = (tid & 3) << 2;

    float acc[4][4] = {};

    for (int k0 = 0; k0 < HID; k0 += BK) {
        float4 a = *(const float4*)(g_dh + (bm + lrow) * HID + k0 + lk);
        As[lk+0][lrow]=a.x; As[lk+1][lrow]=a.y; As[lk+2][lrow]=a.z; As[lk+3][lrow]=a.w;
        float4 v = *(const float4*)(Wout + (bn + lrow) * HID + k0 + lk);
        Bs[lk+0][lrow]=v.x; Bs[lk+1][lrow]=v.y; Bs[lk+2][lrow]=v.z; Bs[lk+3][lrow]=v.w;
        __syncthreads();
        #pragma unroll
        for (int kk = 0; kk < BK; ++kk) {
            float4 av = *(const float4*)&As[kk][ty<<2];
            float4 bv = *(const float4*)&Bs[kk][tx<<2];
            float aa[4]={av.x,av.y,av.z,av.w};
            float bb[4]={bv.x,bv.y,bv.z,bv.w};
            #pragma unroll
            for (int i = 0; i < 4; ++i)
                #pragma unroll
                for (int j = 0; j < 4; ++j)
                    acc[i][j] = fmaf(aa[i], bb[j], acc[i][j]);
        }
        __syncthreads();
    }
    #pragma unroll
    for (int i = 0; i < 4; ++i) {
        int r = bm + (ty<<2) + i;
        #pragma unroll
        for (int j = 0; j < 4; ++j) {
            int c = bn + (tx<<2) + j;
            g_s[r*HID + c] = acc[i][j] + bout[c];
        }
    }
}

// z += dt * softmax_row(s)
__global__ __launch_bounds__(256) void softmax_update_kernel(const float* __restrict__ ts, int t) {
    const int b = blockIdx.x;
    const int tid = threadIdx.x;
    const float* srow = g_s + b * HID;
    float v0 = srow[tid], v1 = srow[tid + 256];

    __shared__ float red[8];
    float m = fmaxf(v0, v1);
    #pragma unroll
    for (int o = 16; o; o >>= 1) m = fmaxf(m, __shfl_xor_sync(0xffffffffu, m, o));
    if ((tid & 31) == 0) red[tid >> 5] = m;
    __syncthreads();
    if (tid == 0) {
        float mm = red[0];
        #pragma unroll
        for (int i = 1; i < 8; ++i) mm = fmaxf(mm, red[i]);
        red[0] = mm;
    }
    __syncthreads();
    m = red[0];
    __syncthreads();

    float e0 = expf(v0 - m), e1 = expf(v1 - m);
    float s = e0 + e1;
    #pragma unroll
    for (int o = 16; o; o >>= 1) s += __shfl_xor_sync(0xffffffffu, s, o);
    if ((tid & 31) == 0) red[tid >> 5] = s;
    __syncthreads();
    if (tid == 0) {
        float ss = 0.f;
        #pragma unroll
        for (int i = 0; i < 8; ++i) ss += red[i];
        red[0] = ss;
    }
    __syncthreads();
    float inv = 1.0f / red[0];
    float dt = ts[t + 1] - ts[t];
    g_z[b*HID + tid      ] += dt * e0 * inv;
    g_z[b*HID + tid + 256] += dt * e1 * inv;
}

// out[b, t] = softmax_row(z[b]) . Wfc + bfc
__global__ __launch_bounds__(256) void softmaxdot_kernel(
    const float* __restrict__ Wfc, const float* __restrict__ bfc,
    float* __restrict__ out, int t)
{
    const int b = blockIdx.x;
    const int tid = threadIdx.x;
    const float* zrow = g_z + b * HID;
    float v0 = zrow[tid], v1 = zrow[tid + 256];

    __shared__ float red_s[8];
    __shared__ float red_d[8];

    float m = fmaxf(v0, v1);
    #pragma unroll
    for (int o = 16; o; o >>= 1) m = fmaxf(m, __shfl_xor_sync(0xffffffffu, m, o));
    if ((tid & 31) == 0) red_s[tid >> 5] = m;
    __syncthreads();
    if (tid == 0) {
        float mm = red_s[0];
        #pragma unroll
        for (int i = 1; i < 8; ++i) mm = fmaxf(mm, red_s[i]);
        red_s[0] = mm;
    }
    __syncthreads();
    m = red_s[0];
    __syncthreads();

    float e0 = expf(v0 - m), e1 = expf(v1 - m);
    float s = e0 + e1;
    float d = e0 * Wfc[tid] + e1 * Wfc[tid + 256];
    #pragma unroll
    for (int o = 16; o; o >>= 1) {
        s += __shfl_xor_sync(0xffffffffu, s, o);
        d += __shfl_xor_sync(0xffffffffu, d, o);
    }
    if ((tid & 31) == 0) { red_s[tid >> 5] = s; red_d[tid >> 5] = d; }
    __syncthreads();
    if (tid == 0) {
        float ss = 0.f, dd = 0.f;
        #pragma unroll
        for (int i = 0; i < 8; ++i) { ss += red_s[i]; dd += red_d[i]; }
        out[b * TSTEPS + t] = dd / ss + bfc[0];
    }
}

extern "C" void kernel_launch(void* const* d_in, const int* in_sizes, int n_in,
                              void* d_out, int out_size) {
    const float* y    = (const float*)d_in[0];
    const float* ts   = (const float*)d_in[1];
    const float* Wi   = (const float*)d_in[2];
    // d_in[3] = Wf — dead in the reference (f computed but unused), skipped.
    const float* Wg   = (const float*)d_in[4];
    const float* Wo   = (const float*)d_in[5];
    const float* Wout = (const float*)d_in[6];
    const float* bout = (const float*)d_in[7];
    const float* Wfc  = (const float*)d_in[8];
    const float* bfc  = (const float*)d_in[9];
    float* out = (float*)d_out;

    copy_z_kernel<<<(BATCH*HID + 255)/256, 256>>>(y);

    dim3 ggrid(BATCH/BM, HID/BN);
    for (int t = 0; t < TSTEPS - 1; ++t) {
        softmaxdot_kernel<<<BATCH, 256>>>(Wfc, bfc, out, t);
        fused_igo_kernel<<<ggrid, 256>>>(Wi, Wg, Wo);
        gemm_bias_kernel<<<ggrid, 256>>>(Wout, bout);
        softmax_update_kernel<<<BATCH, 256>>>(ts, t);
    }
    softmaxdot_kernel<<<BATCH, 256>>>(Wfc, bfc, out, TSTEPS - 1);
}

// round 3
// speedup vs baseline: 4.8583x; 4.8583x over previous
#include <cuda_runtime.h>
#include <cuda_bf16.h>
#include <math.h>
#include <stdint.h>

#define HID    512
#define BATCH  4096
#define TSTEPS 20

// GEMM tiling
#define BM 128
#define BN 64
#define BK 64
#define SK 72                      // padded smem row stride (bf16 elems) -> conflict-free ldmatrix
#define A_EL (BM * SK)             // 9216 elems
#define B_EL (BN * SK)             // 4608 elems
#define F_STAGE_EL (A_EL + 3 * B_EL)
#define F_SMEM (2 * F_STAGE_EL * 2)     // 92160 B
#define W_STAGE_EL (A_EL + B_EL)
#define W_SMEM (2 * W_STAGE_EL * 2)     // 55296 B

// ---------------- scratch (allocation-free rule: __device__ globals) ---------
__device__ __align__(16) float          g_z  [BATCH * HID];
__device__ __align__(16) __nv_bfloat16  g_zb [BATCH * HID];
__device__ __align__(16) __nv_bfloat16  g_dhb[BATCH * HID];
__device__ __align__(16) float          g_s  [BATCH * HID];
__device__ __align__(16) __nv_bfloat16  g_wb [4][HID * HID];   // Wi, Wg, Wo, Wout

// ---------------- helpers ----------------------------------------------------
static __device__ __forceinline__ uint32_t smem_u32(const void* p) {
    uint32_t a;
    asm("{ .reg .u64 t; cvta.to.shared.u64 t, %1; cvt.u32.u64 %0, t; }" : "=r"(a) : "l"(p));
    return a;
}
#define CP16(dst, src) \
    asm volatile("cp.async.cg.shared.global [%0], [%1], 16;" :: "r"(dst), "l"(src))
#define CPC()  asm volatile("cp.async.commit_group;" ::: "memory")
#define CPW1() asm volatile("cp.async.wait_group 1;" ::: "memory")
#define CPW0() asm volatile("cp.async.wait_group 0;" ::: "memory")

__device__ __forceinline__ void ldm4(uint32_t a, uint32_t& r0, uint32_t& r1,
                                     uint32_t& r2, uint32_t& r3) {
    asm volatile("ldmatrix.sync.aligned.m8n8.x4.shared.b16 {%0,%1,%2,%3}, [%4];"
                 : "=r"(r0), "=r"(r1), "=r"(r2), "=r"(r3) : "r"(a));
}
__device__ __forceinline__ void mma16816(float* c, const uint32_t* a, uint32_t b0, uint32_t b1) {
    asm volatile("mma.sync.aligned.m16n8k16.row.col.f32.bf16.bf16.f32 "
                 "{%0,%1,%2,%3},{%4,%5,%6,%7},{%8,%9},{%0,%1,%2,%3};"
                 : "+f"(c[0]), "+f"(c[1]), "+f"(c[2]), "+f"(c[3])
                 : "r"(a[0]), "r"(a[1]), "r"(a[2]), "r"(a[3]), "r"(b0), "r"(b1));
}
__device__ __forceinline__ float sig(float x) { return 1.0f / (1.0f + expf(-x)); }

// ---------------- setup kernels ---------------------------------------------
__global__ void w2bf_kernel(const float* __restrict__ Wi, const float* __restrict__ Wg,
                            const float* __restrict__ Wo, const float* __restrict__ Wout) {
    int i = blockIdx.x * blockDim.x + threadIdx.x;
    if (i >= 4 * HID * HID) return;
    int m = i >> 18, r = i & (HID * HID - 1);
    const float* src = (m == 0) ? Wi : (m == 1) ? Wg : (m == 2) ? Wo : Wout;
    g_wb[m][r] = __float2bfloat16_rn(src[r]);
}

__global__ void copy_z_kernel(const float* __restrict__ y) {
    int i = blockIdx.x * blockDim.x + threadIdx.x;
    if (i < BATCH * HID) { float v = y[i]; g_z[i] = v; g_zb[i] = __float2bfloat16_rn(v); }
}

// ---------------- async stage loaders ----------------------------------------
__device__ __forceinline__ void f_issue(uint32_t sb, int tid, int bm, int bn, int ch) {
    const uint32_t base = sb + (uint32_t)(ch & 1) * (F_STAGE_EL * 2);
    const int k0 = ch * BK;
    #pragma unroll
    for (int i = 0; i < 10; ++i) {
        int idx = i * 256 + tid;
        uint32_t dst; const __nv_bfloat16* src;
        if (idx < 1024) {                       // A tile: 128 rows x 8 x 16B
            int row = idx >> 3, c = idx & 7;
            dst = base + (uint32_t)(row * SK + c * 8) * 2;
            src = g_zb + (bm + row) * HID + k0 + c * 8;
        } else {                                // B tiles: 3 x 64 rows x 8 x 16B
            int ib = idx - 1024;
            int w = ib >> 9, row = (ib >> 3) & 63, c = ib & 7;
            dst = base + (uint32_t)(A_EL + w * B_EL + row * SK + c * 8) * 2;
            src = g_wb[w] + (bn + row) * HID + k0 + c * 8;
        }
        CP16(dst, src);
    }
    CPC();
}

__device__ __forceinline__ void w_issue(uint32_t sb, int tid, int bm, int bn, int ch) {
    const uint32_t base = sb + (uint32_t)(ch & 1) * (W_STAGE_EL * 2);
    const int k0 = ch * BK;
    #pragma unroll
    for (int i = 0; i < 6; ++i) {
        int idx = i * 256 + tid;
        uint32_t dst; const __nv_bfloat16* src;
        if (idx < 1024) {
            int row = idx >> 3, c = idx & 7;
            dst = base + (uint32_t)(row * SK + c * 8) * 2;
            src = g_dhb + (bm + row) * HID + k0 + c * 8;
        } else {
            int ib = idx - 1024;
            int row = (ib >> 3) & 63, c = ib & 7;
            dst = base + (uint32_t)(A_EL + row * SK + c * 8) * 2;
            src = g_wb[3] + (bn + row) * HID + k0 + c * 8;
        }
        CP16(dst, src);
    }
    CPC();
}

// ---------------- fused i/g/o HMMA GEMM --------------------------------------
// dh = sigmoid(z@Wo^T) * tanh( sigmoid(z@Wi^T) * tanh(z@Wg^T) ) -> g_dhb (bf16)
__global__ __launch_bounds__(256, 1) void fused_igo_mma() {
    extern __shared__ __nv_bfloat16 sm[];
    const uint32_t sb = smem_u32(sm);
    const int tid = threadIdx.x, lane = tid & 31;
    const int warpM = (tid >> 5) & 3, warpN = tid >> 7;      // 4 x 2 warps
    const int bm = blockIdx.x * BM, bn = blockIdx.y * BN;

    float ai[2][4][4], ag[2][4][4], ao[2][4][4];
    #pragma unroll
    for (int x = 0; x < 2; ++x)
        #pragma unroll
        for (int y = 0; y < 4; ++y)
            #pragma unroll
            for (int zz = 0; zz < 4; ++zz) { ai[x][y][zz] = 0.f; ag[x][y][zz] = 0.f; ao[x][y][zz] = 0.f; }

    // per-lane ldmatrix address components (constant over loop)
    const int am = warpM * 32 + (lane & 15);
    const int ak = (lane >> 4) << 3;
    const int bnrow = warpN * 32 + (((lane >> 3) >> 1) << 3) + (lane & 7);
    const int bk = ((lane >> 3) & 1) << 3;

    f_issue(sb, tid, bm, bn, 0);
    for (int ch = 0; ch < HID / BK; ++ch) {
        if (ch < HID / BK - 1) { f_issue(sb, tid, bm, bn, ch + 1); CPW1(); }
        else                   { CPW0(); }
        __syncthreads();
        const uint32_t base  = sb + (uint32_t)(ch & 1) * (F_STAGE_EL * 2);
        const uint32_t baseA = base;
        const uint32_t baseI = base + A_EL * 2;
        const uint32_t baseG = baseI + B_EL * 2;
        const uint32_t baseO = baseG + B_EL * 2;
        #pragma unroll
        for (int kk = 0; kk < BK; kk += 16) {
            uint32_t a[2][4];
            uint32_t aaddr = baseA + (uint32_t)(am * SK + ak + kk) * 2;
            ldm4(aaddr,               a[0][0], a[0][1], a[0][2], a[0][3]);
            ldm4(aaddr + 16 * SK * 2, a[1][0], a[1][1], a[1][2], a[1][3]);
            const uint32_t boff0 = (uint32_t)(bnrow * SK + bk + kk) * 2;
            const uint32_t boff1 = boff0 + 16 * SK * 2;
            uint32_t b0, b1, b2, b3;
            // Wi
            ldm4(baseI + boff0, b0, b1, b2, b3);
            mma16816(ai[0][0], a[0], b0, b1); mma16816(ai[0][1], a[0], b2, b3);
            mma16816(ai[1][0], a[1], b0, b1); mma16816(ai[1][1], a[1], b2, b3);
            ldm4(baseI + boff1, b0, b1, b2, b3);
            mma16816(ai[0][2], a[0], b0, b1); mma16816(ai[0][3], a[0], b2, b3);
            mma16816(ai[1][2], a[1], b0, b1); mma16816(ai[1][3], a[1], b2, b3);
            // Wg
            ldm4(baseG + boff0, b0, b1, b2, b3);
            mma16816(ag[0][0], a[0], b0, b1); mma16816(ag[0][1], a[0], b2, b3);
            mma16816(ag[1][0], a[1], b0, b1); mma16816(ag[1][1], a[1], b2, b3);
            ldm4(baseG + boff1, b0, b1, b2, b3);
            mma16816(ag[0][2], a[0], b0, b1); mma16816(ag[0][3], a[0], b2, b3);
            mma16816(ag[1][2], a[1], b0, b1); mma16816(ag[1][3], a[1], b2, b3);
            // Wo
            ldm4(baseO + boff0, b0, b1, b2, b3);
            mma16816(ao[0][0], a[0], b0, b1); mma16816(ao[0][1], a[0], b2, b3);
            mma16816(ao[1][0], a[1], b0, b1); mma16816(ao[1][1], a[1], b2, b3);
            ldm4(baseO + boff1, b0, b1, b2, b3);
            mma16816(ao[0][2], a[0], b0, b1); mma16816(ao[0][3], a[0], b2, b3);
            mma16816(ao[1][2], a[1], b0, b1); mma16816(ao[1][3], a[1], b2, b3);
        }
        __syncthreads();
    }

    // epilogue: dh activation, bf16 store
    #pragma unroll
    for (int mi = 0; mi < 2; ++mi) {
        const int r = bm + warpM * 32 + mi * 16 + (lane >> 2);
        #pragma unroll
        for (int ni = 0; ni < 4; ++ni) {
            const int col = bn + warpN * 32 + ni * 8 + ((lane & 3) << 1);
            float I0 = sig(ai[mi][ni][0]), G0 = tanhf(ag[mi][ni][0]), O0 = sig(ao[mi][ni][0]);
            float I1 = sig(ai[mi][ni][1]), G1 = tanhf(ag[mi][ni][1]), O1 = sig(ao[mi][ni][1]);
            float I2 = sig(ai[mi][ni][2]), G2 = tanhf(ag[mi][ni][2]), O2 = sig(ao[mi][ni][2]);
            float I3 = sig(ai[mi][ni][3]), G3 = tanhf(ag[mi][ni][3]), O3 = sig(ao[mi][ni][3]);
            *(__nv_bfloat162*)(g_dhb + r * HID + col) =
                __floats2bfloat162_rn(O0 * tanhf(I0 * G0), O1 * tanhf(I1 * G1));
            *(__nv_bfloat162*)(g_dhb + (r + 8) * HID + col) =
                __floats2bfloat162_rn(O2 * tanhf(I2 * G2), O3 * tanhf(I3 * G3));
        }
    }
}

// ---------------- Wout HMMA GEMM: s = dh @ Wout^T + bout ---------------------
__global__ __launch_bounds__(256, 1) void wout_mma(const float* __restrict__ bout) {
    extern __shared__ __nv_bfloat16 sm[];
    const uint32_t sb = smem_u32(sm);
    const int tid = threadIdx.x, lane = tid & 31;
    const int warpM = (tid >> 5) & 3, warpN = tid >> 7;
    const int bm = blockIdx.x * BM, bn = blockIdx.y * BN;

    float acc[2][4][4];
    #pragma unroll
    for (int x = 0; x < 2; ++x)
        #pragma unroll
        for (int y = 0; y < 4; ++y)
            #pragma unroll
            for (int zz = 0; zz < 4; ++zz) acc[x][y][zz] = 0.f;

    const int am = warpM * 32 + (lane & 15);
    const int ak = (lane >> 4) << 3;
    const int bnrow = warpN * 32 + (((lane >> 3) >> 1) << 3) + (lane & 7);
    const int bk = ((lane >> 3) & 1) << 3;

    w_issue(sb, tid, bm, bn, 0);
    for (int ch = 0; ch < HID / BK; ++ch) {
        if (ch < HID / BK - 1) { w_issue(sb, tid, bm, bn, ch + 1); CPW1(); }
        else                   { CPW0(); }
        __syncthreads();
        const uint32_t base  = sb + (uint32_t)(ch & 1) * (W_STAGE_EL * 2);
        const uint32_t baseB = base + A_EL * 2;
        #pragma unroll
        for (int kk = 0; kk < BK; kk += 16) {
            uint32_t a[2][4];
            uint32_t aaddr = base + (uint32_t)(am * SK + ak + kk) * 2;
            ldm4(aaddr,               a[0][0], a[0][1], a[0][2], a[0][3]);
            ldm4(aaddr + 16 * SK * 2, a[1][0], a[1][1], a[1][2], a[1][3]);
            const uint32_t boff0 = (uint32_t)(bnrow * SK + bk + kk) * 2;
            const uint32_t boff1 = boff0 + 16 * SK * 2;
            uint32_t b0, b1, b2, b3;
            ldm4(baseB + boff0, b0, b1, b2, b3);
            mma16816(acc[0][0], a[0], b0, b1); mma16816(acc[0][1], a[0], b2, b3);
            mma16816(acc[1][0], a[1], b0, b1); mma16816(acc[1][1], a[1], b2, b3);
            ldm4(baseB + boff1, b0, b1, b2, b3);
            mma16816(acc[0][2], a[0], b0, b1); mma16816(acc[0][3], a[0], b2, b3);
            mma16816(acc[1][2], a[1], b0, b1); mma16816(acc[1][3], a[1], b2, b3);
        }
        __syncthreads();
    }

    #pragma unroll
    for (int mi = 0; mi < 2; ++mi) {
        const int r = bm + warpM * 32 + mi * 16 + (lane >> 2);
        #pragma unroll
        for (int ni = 0; ni < 4; ++ni) {
            const int col = bn + warpN * 32 + ni * 8 + ((lane & 3) << 1);
            float b0v = bout[col], b1v = bout[col + 1];
            float2 lo = { acc[mi][ni][0] + b0v, acc[mi][ni][1] + b1v };
            float2 hi = { acc[mi][ni][2] + b0v, acc[mi][ni][3] + b1v };
            *(float2*)(g_s + r * HID + col)       = lo;
            *(float2*)(g_s + (r + 8) * HID + col) = hi;
        }
    }
}

// ---------------- fused softmax(s)->z update + softmax(z)->out[t+1] ----------
__global__ __launch_bounds__(256) void update_out_kernel(
    const float* __restrict__ ts, const float* __restrict__ Wfc,
    const float* __restrict__ bfc, float* __restrict__ out, int t)
{
    const int b = blockIdx.x;
    const int tid = threadIdx.x;
    __shared__ float red_a[8], red_b[8];

    // phase 1: softmax over s-row, z += dt * p
    float v0 = g_s[b * HID + tid], v1 = g_s[b * HID + tid + 256];
    float m = fmaxf(v0, v1);
    #pragma unroll
    for (int o = 16; o; o >>= 1) m = fmaxf(m, __shfl_xor_sync(0xffffffffu, m, o));
    if ((tid & 31) == 0) red_a[tid >> 5] = m;
    __syncthreads();
    if (tid == 0) {
        float mm = red_a[0];
        #pragma unroll
        for (int i = 1; i < 8; ++i) mm = fmaxf(mm, red_a[i]);
        red_a[0] = mm;
    }
    __syncthreads();
    m = red_a[0];
    __syncthreads();
    float e0 = expf(v0 - m), e1 = expf(v1 - m);
    float s = e0 + e1;
    #pragma unroll
    for (int o = 16; o; o >>= 1) s += __shfl_xor_sync(0xffffffffu, s, o);
    if ((tid & 31) == 0) red_a[tid >> 5] = s;
    __syncthreads();
    if (tid == 0) {
        float ss = 0.f;
        #pragma unroll
        for (int i = 0; i < 8; ++i) ss += red_a[i];
        red_a[0] = ss;
    }
    __syncthreads();
    float inv = 1.0f / red_a[0];
    float dt = ts[t + 1] - ts[t];
    float z0 = g_z[b * HID + tid      ] + dt * e0 * inv;
    float z1 = g_z[b * HID + tid + 256] + dt * e1 * inv;
    g_z[b * HID + tid      ] = z0;
    g_z[b * HID + tid + 256] = z1;
    g_zb[b * HID + tid      ] = __float2bfloat16_rn(z0);
    g_zb[b * HID + tid + 256] = __float2bfloat16_rn(z1);
    __syncthreads();

    // phase 2: softmax over new z, dot Wfc -> out[b][t+1]
    m = fmaxf(z0, z1);
    #pragma unroll
    for (int o = 16; o; o >>= 1) m = fmaxf(m, __shfl_xor_sync(0xffffffffu, m, o));
    if ((tid & 31) == 0) red_a[tid >> 5] = m;
    __syncthreads();
    if (tid == 0) {
        float mm = red_a[0];
        #pragma unroll
        for (int i = 1; i < 8; ++i) mm = fmaxf(mm, red_a[i]);
        red_a[0] = mm;
    }
    __syncthreads();
    m = red_a[0];
    __syncthreads();
    e0 = expf(z0 - m); e1 = expf(z1 - m);
    s = e0 + e1;
    float d = e0 * Wfc[tid] + e1 * Wfc[tid + 256];
    #pragma unroll
    for (int o = 16; o; o >>= 1) {
        s += __shfl_xor_sync(0xffffffffu, s, o);
        d += __shfl_xor_sync(0xffffffffu, d, o);
    }
    if ((tid & 31) == 0) { red_a[tid >> 5] = s; red_b[tid >> 5] = d; }
    __syncthreads();
    if (tid == 0) {
        float ss = 0.f, dd = 0.f;
        #pragma unroll
        for (int i = 0; i < 8; ++i) { ss += red_a[i]; dd += red_b[i]; }
        out[b * TSTEPS + t + 1] = dd / ss + bfc[0];
    }
}

// out[b, 0] = softmax_row(z[b]) . Wfc + bfc  (initial readout)
__global__ __launch_bounds__(256) void softmaxdot_kernel(
    const float* __restrict__ Wfc, const float* __restrict__ bfc,
    float* __restrict__ out)
{
    const int b = blockIdx.x;
    const int tid = threadIdx.x;
    float v0 = g_z[b * HID + tid], v1 = g_z[b * HID + tid + 256];
    __shared__ float red_s[8], red_d[8];

    float m = fmaxf(v0, v1);
    #pragma unroll
    for (int o = 16; o; o >>= 1) m = fmaxf(m, __shfl_xor_sync(0xffffffffu, m, o));
    if ((tid & 31) == 0) red_s[tid >> 5] = m;
    __syncthreads();
    if (tid == 0) {
        float mm = red_s[0];
        #pragma unroll
        for (int i = 1; i < 8; ++i) mm = fmaxf(mm, red_s[i]);
        red_s[0] = mm;
    }
    __syncthreads();
    m = red_s[0];
    __syncthreads();
    float e0 = expf(v0 - m), e1 = expf(v1 - m);
    float s = e0 + e1;
    float d = e0 * Wfc[tid] + e1 * Wfc[tid + 256];
    #pragma unroll
    for (int o = 16; o; o >>= 1) {
        s += __shfl_xor_sync(0xffffffffu, s, o);
        d += __shfl_xor_sync(0xffffffffu, d, o);
    }
    if ((tid & 31) == 0) { red_s[tid >> 5] = s; red_d[tid >> 5] = d; }
    __syncthreads();
    if (tid == 0) {
        float ss = 0.f, dd = 0.f;
        #pragma unroll
        for (int i = 0; i < 8; ++i) { ss += red_s[i]; dd += red_d[i]; }
        out[b * TSTEPS + 0] = dd / ss + bfc[0];
    }
}

// ---------------- launch -----------------------------------------------------
extern "C" void kernel_launch(void* const* d_in, const int* in_sizes, int n_in,
                              void* d_out, int out_size) {
    const float* y    = (const float*)d_in[0];
    const float* ts   = (const float*)d_in[1];
    const float* Wi   = (const float*)d_in[2];
    // d_in[3] = Wf — dead in the reference (f computed but unused), skipped.
    const float* Wg   = (const float*)d_in[4];
    const float* Wo   = (const float*)d_in[5];
    const float* Wout = (const float*)d_in[6];
    const float* bout = (const float*)d_in[7];
    const float* Wfc  = (const float*)d_in[8];
    const float* bfc  = (const float*)d_in[9];
    float* out = (float*)d_out;

    cudaFuncSetAttribute(fused_igo_mma, cudaFuncAttributeMaxDynamicSharedMemorySize, F_SMEM);
    cudaFuncSetAttribute(wout_mma,      cudaFuncAttributeMaxDynamicSharedMemorySize, W_SMEM);

    w2bf_kernel<<<(4 * HID * HID + 255) / 256, 256>>>(Wi, Wg, Wo, Wout);
    copy_z_kernel<<<(BATCH * HID + 255) / 256, 256>>>(y);
    softmaxdot_kernel<<<BATCH, 256>>>(Wfc, bfc, out);

    dim3 ggrid(BATCH / BM, HID / BN);
    for (int t = 0; t < TSTEPS - 1; ++t) {
        fused_igo_mma<<<ggrid, 256, F_SMEM>>>();
        wout_mma<<<ggrid, 256, W_SMEM>>>(bout);
        update_out_kernel<<<BATCH, 256>>>(ts, Wfc, bfc, out, t);
    }
}